// round 13
// baseline (speedup 1.0000x reference)
#include <cuda_runtime.h>
#include <math.h>

// Batched SIREN MLP: coords (B,N,2) f32, flat_weights (B,921) f32 -> (B,N,1) f32
// 2->20->20->20->1, hidden act sin(20*(Wx+b)), final clip [0,1].
//
// Numerics contract (R4-R12):
//  - dots: UNCONTRACTED scalar round(mul)+round(add), k ascending, acc from 0
//    (FMA contraction fails; packed f32x2 fails)
//  - +b, *20 separate rounded ops
//  - sine: magic-add CW2 + Taylor, abs err ~3e-8 (validated @ 7.716e-4)
//
// R13: 2 points/thread (halves LDS/pt, doubles ILP) at BLOCK=128 with
// launch_bounds(128,4) so four 128-thread blocks (16 warps) co-reside —
// R11's identical body at block=256 hit the 64K-reg boundary and dropped to
// 8 warps. Also: cos z^5 Taylor term dropped (err 2.5e-8, ~1.2e-5 at output).

#define HID 20
#define PSZ 921

// Branch-free sine, |x| <= ~1e5. Abs err ~3e-8.
__device__ __forceinline__ float sin_fast(float x) {
    constexpr float  INV_PIO2 = 0.63661977236758134308f;
    constexpr float  MAGIC = 12582912.0f;  // 1.5 * 2^23
    constexpr double PIO2 = 1.5707963267948966192313216916398;
    constexpr float  P1 = (float)PIO2;
    constexpr float  P2 = (float)(PIO2 - (double)P1);

    float t = fmaf(x, INV_PIO2, MAGIC);
    unsigned q = __float_as_uint(t);        // low 2 bits == k mod 4
    float kf = t - MAGIC;

    float r = fmaf(-kf, P1, x);
    r = fmaf(-kf, P2, r);

    float z = r * r;

    float p = fmaf(z,  2.75573192239858907e-6f, -1.98412698412698413e-4f);
    p = fmaf(z, p,  8.33333333333333322e-3f);
    p = fmaf(z, p, -1.66666666666666667e-1f);
    float sinv = fmaf(r * z, p, r);

    float c = fmaf(z,  2.48015873015873016e-5f, -1.38888888888888889e-3f);
    c = fmaf(z, c,  4.16666666666666644e-2f);
    c = fmaf(z, c, -0.5f);
    float cosv = fmaf(z, c, 1.0f);

    float v = (q & 1u) ? cosv : sinv;
    return __uint_as_float(__float_as_uint(v) ^ ((q & 2u) << 30));
}

__global__ __launch_bounds__(128, 4) void siren_kernel(
    const float* __restrict__ coords,
    const float* __restrict__ weights,
    float* __restrict__ out,
    int N)
{
    __shared__ __align__(16) float s[PSZ];
    const int b = blockIdx.y;

    const float* wb = weights + (size_t)b * PSZ;
    for (int i = threadIdx.x; i < PSZ; i += blockDim.x) s[i] = wb[i];
    __syncthreads();

    const int n0 = blockIdx.x * 256 + threadIdx.x;
    const int n1 = n0 + 128;
    if (n0 >= N) return;
    const bool has1 = (n1 < N);

    const float2* cb =
        reinterpret_cast<const float2*>(coords + (size_t)b * (size_t)N * 2);
    const float2 cA = cb[n0];
    const float2 cB = has1 ? cb[n1] : cA;

    float a0A[HID], a1A[HID];
    float a0B[HID], a1B[HID];

    // ---- Layer 1: 2 -> 20 ----
    #pragma unroll
    for (int o = 0; o < HID; o++) {
        float2 w = *reinterpret_cast<const float2*>(&s[2 * o]);
        float bias = s[40 + o];
        float aA = __fadd_rn(__fmul_rn(w.x, cA.x), __fmul_rn(w.y, cA.y));
        float aB = __fadd_rn(__fmul_rn(w.x, cB.x), __fmul_rn(w.y, cB.y));
        aA = __fadd_rn(aA, bias);
        aB = __fadd_rn(aB, bias);
        a0A[o] = sin_fast(__fmul_rn(20.0f, aA));
        a0B[o] = sin_fast(__fmul_rn(20.0f, aB));
    }

    // ---- Layer 2: 20 -> 20 ---- (LDS.128 rows shared by both points)
    #pragma unroll
    for (int o = 0; o < HID; o++) {
        const float4* wrow = reinterpret_cast<const float4*>(&s[60 + o * HID]);
        float aA = 0.0f, aB = 0.0f;
        #pragma unroll
        for (int v = 0; v < HID / 4; v++) {
            float4 w = wrow[v];
            aA = __fadd_rn(aA, __fmul_rn(w.x, a0A[4 * v + 0]));
            aB = __fadd_rn(aB, __fmul_rn(w.x, a0B[4 * v + 0]));
            aA = __fadd_rn(aA, __fmul_rn(w.y, a0A[4 * v + 1]));
            aB = __fadd_rn(aB, __fmul_rn(w.y, a0B[4 * v + 1]));
            aA = __fadd_rn(aA, __fmul_rn(w.z, a0A[4 * v + 2]));
            aB = __fadd_rn(aB, __fmul_rn(w.z, a0B[4 * v + 2]));
            aA = __fadd_rn(aA, __fmul_rn(w.w, a0A[4 * v + 3]));
            aB = __fadd_rn(aB, __fmul_rn(w.w, a0B[4 * v + 3]));
        }
        float bias = s[460 + o];
        aA = __fadd_rn(aA, bias);
        aB = __fadd_rn(aB, bias);
        a1A[o] = sin_fast(__fmul_rn(20.0f, aA));
        a1B[o] = sin_fast(__fmul_rn(20.0f, aB));
    }

    // ---- Layer 3: 20 -> 20 ----
    #pragma unroll
    for (int o = 0; o < HID; o++) {
        const float4* wrow = reinterpret_cast<const float4*>(&s[480 + o * HID]);
        float aA = 0.0f, aB = 0.0f;
        #pragma unroll
        for (int v = 0; v < HID / 4; v++) {
            float4 w = wrow[v];
            aA = __fadd_rn(aA, __fmul_rn(w.x, a1A[4 * v + 0]));
            aB = __fadd_rn(aB, __fmul_rn(w.x, a1B[4 * v + 0]));
            aA = __fadd_rn(aA, __fmul_rn(w.y, a1A[4 * v + 1]));
            aB = __fadd_rn(aB, __fmul_rn(w.y, a1B[4 * v + 1]));
            aA = __fadd_rn(aA, __fmul_rn(w.z, a1A[4 * v + 2]));
            aB = __fadd_rn(aB, __fmul_rn(w.z, a1B[4 * v + 2]));
            aA = __fadd_rn(aA, __fmul_rn(w.w, a1A[4 * v + 3]));
            aB = __fadd_rn(aB, __fmul_rn(w.w, a1B[4 * v + 3]));
        }
        float bias = s[880 + o];
        aA = __fadd_rn(aA, bias);
        aB = __fadd_rn(aB, bias);
        a0A[o] = sin_fast(__fmul_rn(20.0f, aA));
        a0B[o] = sin_fast(__fmul_rn(20.0f, aB));
    }

    // ---- Layer 4: 20 -> 1, clip ----
    {
        const float4* wrow = reinterpret_cast<const float4*>(&s[900]);
        float aA = 0.0f, aB = 0.0f;
        #pragma unroll
        for (int v = 0; v < HID / 4; v++) {
            float4 w = wrow[v];
            aA = __fadd_rn(aA, __fmul_rn(w.x, a0A[4 * v + 0]));
            aB = __fadd_rn(aB, __fmul_rn(w.x, a0B[4 * v + 0]));
            aA = __fadd_rn(aA, __fmul_rn(w.y, a0A[4 * v + 1]));
            aB = __fadd_rn(aB, __fmul_rn(w.y, a0B[4 * v + 1]));
            aA = __fadd_rn(aA, __fmul_rn(w.z, a0A[4 * v + 2]));
            aB = __fadd_rn(aB, __fmul_rn(w.z, a0B[4 * v + 2]));
            aA = __fadd_rn(aA, __fmul_rn(w.w, a0A[4 * v + 3]));
            aB = __fadd_rn(aB, __fmul_rn(w.w, a0B[4 * v + 3]));
        }
        float bias = s[920];
        aA = __fadd_rn(aA, bias);
        aB = __fadd_rn(aB, bias);
        float* ob = out + (size_t)b * (size_t)N;
        ob[n0] = fminf(fmaxf(aA, 0.0f), 1.0f);
        if (has1) ob[n1] = fminf(fmaxf(aB, 0.0f), 1.0f);
    }
}

extern "C" void kernel_launch(void* const* d_in, const int* in_sizes, int n_in,
                              void* d_out, int out_size) {
    const float* coords  = (const float*)d_in[0];   // (B, N, 2)
    const float* weights = (const float*)d_in[1];   // (B, 921)
    float* out = (float*)d_out;                     // (B, N, 1)

    const int B = in_sizes[1] / PSZ;
    const int N = in_sizes[0] / (2 * B);

    dim3 block(128);
    dim3 grid((N + 255) / 256, B);
    siren_kernel<<<grid, block>>>(coords, weights, out, N);
}

// round 14
// speedup vs baseline: 1.3472x; 1.3472x over previous
#include <cuda_runtime.h>
#include <math.h>

// Batched SIREN MLP: coords (B,N,2) f32, flat_weights (B,921) f32 -> (B,N,1) f32
// 2->20->20->20->1, hidden act sin(20*(Wx+b)), final clip [0,1].
//
// Numerics contract (R4-R13):
//  - dots: UNCONTRACTED scalar round(mul)+round(add), k ascending, acc from 0
//    (FMA contraction fails; packed f32x2 fails)
//  - +b, *20 separate rounded ops
//  - sine: abs err ~1e-7 class is safe (measured sensitivity: 2.5e-8 sine
//    change moved output rel_err by 1.2e-6; margin is 2.3e-4)
//
// Occupancy contract (R11/R13 lesson): regs MUST stay <= 64 so four
// 256-thread blocks (32 warps) co-reside; 2-pt/thread (>=96 regs) retired.
//
// R14: pi-period sine — k=round(x/pi), r=x-k*pi (CW2), ONE odd Taylor-13
// poly over |r|<=pi/2, sign=(-1)^k via XOR. ~13 inst vs ~17 (no cos poly,
// no select). Plus layer-1 weights as LDS.128.

#define HID 20
#define PSZ 921

// Branch-free sine via pi-reduction. |x| <= ~3000. Abs err ~1e-7 worst case.
__device__ __forceinline__ float sin_fast(float x) {
    constexpr float  INV_PI = 0.31830988618379067154f;
    constexpr float  MAGIC = 12582912.0f;  // 1.5 * 2^23
    constexpr double PID = 3.14159265358979323846264338328;
    constexpr float  PI1 = (float)PID;
    constexpr float  PI2 = (float)(PID - (double)PI1);

    float t = fmaf(x, INV_PI, MAGIC);
    unsigned q = __float_as_uint(t);        // low bit == k mod 2
    float kf = t - MAGIC;

    float r = fmaf(-kf, PI1, x);
    r = fmaf(-kf, PI2, r);

    float z = r * r;

    // sin(r), odd Taylor through r^13 (trunc err 6.7e-10 at pi/2)
    float p = fmaf(z,  1.60590438368216146e-10f, -2.50521083854417188e-8f);
    p = fmaf(z, p,  2.75573192239858907e-6f);
    p = fmaf(z, p, -1.98412698412698413e-4f);
    p = fmaf(z, p,  8.33333333333333322e-3f);
    p = fmaf(z, p, -1.66666666666666667e-1f);
    float sinv = fmaf(r * z, p, r);

    // sign flip by (-1)^k
    return __uint_as_float(__float_as_uint(sinv) ^ (q << 31));
}

__global__ __launch_bounds__(256) void siren_kernel(
    const float* __restrict__ coords,
    const float* __restrict__ weights,
    float* __restrict__ out,
    int N)
{
    __shared__ __align__(16) float s[PSZ];
    const int b = blockIdx.y;

    const float* wb = weights + (size_t)b * PSZ;
    for (int i = threadIdx.x; i < PSZ; i += blockDim.x) s[i] = wb[i];
    __syncthreads();

    const int n = blockIdx.x * blockDim.x + threadIdx.x;
    if (n >= N) return;

    const float2 c =
        reinterpret_cast<const float2*>(coords + (size_t)b * (size_t)N * 2)[n];

    float a0[HID];
    float a1[HID];

    // ---- Layer 1: 2 -> 20 ---- (LDS.128 covers weights for 2 outputs)
    #pragma unroll
    for (int o2 = 0; o2 < HID / 2; o2++) {
        float4 w = *reinterpret_cast<const float4*>(&s[4 * o2]);
        int oA = 2 * o2, oB = 2 * o2 + 1;
        float accA = __fadd_rn(__fmul_rn(w.x, c.x), __fmul_rn(w.y, c.y));
        float accB = __fadd_rn(__fmul_rn(w.z, c.x), __fmul_rn(w.w, c.y));
        accA = __fadd_rn(accA, s[40 + oA]);
        accB = __fadd_rn(accB, s[40 + oB]);
        a0[oA] = sin_fast(__fmul_rn(20.0f, accA));
        a0[oB] = sin_fast(__fmul_rn(20.0f, accB));
    }

    // ---- Layer 2: 20 -> 20 ---- (sequential uncontracted; LDS.128 weights)
    #pragma unroll
    for (int o = 0; o < HID; o++) {
        const float4* wrow = reinterpret_cast<const float4*>(&s[60 + o * HID]);
        float acc = 0.0f;
        #pragma unroll
        for (int v = 0; v < HID / 4; v++) {
            float4 w = wrow[v];
            acc = __fadd_rn(acc, __fmul_rn(w.x, a0[4 * v + 0]));
            acc = __fadd_rn(acc, __fmul_rn(w.y, a0[4 * v + 1]));
            acc = __fadd_rn(acc, __fmul_rn(w.z, a0[4 * v + 2]));
            acc = __fadd_rn(acc, __fmul_rn(w.w, a0[4 * v + 3]));
        }
        acc = __fadd_rn(acc, s[460 + o]);
        a1[o] = sin_fast(__fmul_rn(20.0f, acc));
    }

    // ---- Layer 3: 20 -> 20 ----
    #pragma unroll
    for (int o = 0; o < HID; o++) {
        const float4* wrow = reinterpret_cast<const float4*>(&s[480 + o * HID]);
        float acc = 0.0f;
        #pragma unroll
        for (int v = 0; v < HID / 4; v++) {
            float4 w = wrow[v];
            acc = __fadd_rn(acc, __fmul_rn(w.x, a1[4 * v + 0]));
            acc = __fadd_rn(acc, __fmul_rn(w.y, a1[4 * v + 1]));
            acc = __fadd_rn(acc, __fmul_rn(w.z, a1[4 * v + 2]));
            acc = __fadd_rn(acc, __fmul_rn(w.w, a1[4 * v + 3]));
        }
        acc = __fadd_rn(acc, s[880 + o]);
        a0[o] = sin_fast(__fmul_rn(20.0f, acc));
    }

    // ---- Layer 4: 20 -> 1, clip ----
    {
        const float4* wrow = reinterpret_cast<const float4*>(&s[900]);
        float acc = 0.0f;
        #pragma unroll
        for (int v = 0; v < HID / 4; v++) {
            float4 w = wrow[v];
            acc = __fadd_rn(acc, __fmul_rn(w.x, a0[4 * v + 0]));
            acc = __fadd_rn(acc, __fmul_rn(w.y, a0[4 * v + 1]));
            acc = __fadd_rn(acc, __fmul_rn(w.z, a0[4 * v + 2]));
            acc = __fadd_rn(acc, __fmul_rn(w.w, a0[4 * v + 3]));
        }
        acc = __fadd_rn(acc, s[920]);
        out[(size_t)b * (size_t)N + n] = fminf(fmaxf(acc, 0.0f), 1.0f);
    }
}

extern "C" void kernel_launch(void* const* d_in, const int* in_sizes, int n_in,
                              void* d_out, int out_size) {
    const float* coords  = (const float*)d_in[0];   // (B, N, 2)
    const float* weights = (const float*)d_in[1];   // (B, 921)
    float* out = (float*)d_out;                     // (B, N, 1)

    const int B = in_sizes[1] / PSZ;
    const int N = in_sizes[0] / (2 * B);

    dim3 block(256);
    dim3 grid((N + 255) / 256, B);
    siren_kernel<<<grid, block>>>(coords, weights, out, N);
}